// round 2
// baseline (speedup 1.0000x reference)
#include <cuda_runtime.h>
#include <cuda_bf16.h>
#include <math.h>
#include <stdint.h>

// ---------------- scratch (device globals: no allocation allowed) ----------
__device__ float g_q[2048 * 4096];
__device__ float g_k[2048 * 1024];
__device__ float g_v[2048 * 1024];
__device__ float g_attn[2048 * 4096];
__device__ float g_cos[2048 * 64];
__device__ float g_sin[2048 * 64];

// ==================== split-bf16 tensor-core GEMM ==========================
// C[M,N] = A[M,K] @ B[K,N], all fp32 in gmem. Internally splits each operand
// into hi/lo bf16 and computes hi*hi + hi*lo + lo*hi on HMMA (m16n8k16).
// BM=BN=128, BK=32, 256 threads (8 warps as 4x2), warp tile 32x64.

#define KPAD 40   // bf16 elems per smem row (32 data + 8 pad) -> conflict-free

__device__ __forceinline__ void mma16816(float acc[4], const uint32_t a[4],
                                         const uint32_t b[2]) {
    asm volatile(
        "mma.sync.aligned.m16n8k16.row.col.f32.bf16.bf16.f32 "
        "{%0,%1,%2,%3}, {%4,%5,%6,%7}, {%8,%9}, {%0,%1,%2,%3};\n"
        : "+f"(acc[0]), "+f"(acc[1]), "+f"(acc[2]), "+f"(acc[3])
        : "r"(a[0]), "r"(a[1]), "r"(a[2]), "r"(a[3]), "r"(b[0]), "r"(b[1]));
}

__device__ __forceinline__ void split1(float x, __nv_bfloat16& hi, __nv_bfloat16& lo) {
    hi = __float2bfloat16(x);
    lo = __float2bfloat16(x - __bfloat162float(hi));
}

__device__ __forceinline__ void split2pack(float x, float y, uint32_t& hi, uint32_t& lo) {
    __nv_bfloat16 hx, lx, hy, ly;
    split1(x, hx, lx);
    split1(y, hy, ly);
    hi = ((uint32_t)__bfloat16_as_ushort(hy) << 16) | __bfloat16_as_ushort(hx);
    lo = ((uint32_t)__bfloat16_as_ushort(ly) << 16) | __bfloat16_as_ushort(lx);
}

__global__ __launch_bounds__(256) void hgemm_split(const float* __restrict__ A,
                                                   const float* __restrict__ B,
                                                   float* __restrict__ C,
                                                   int M, int N, int K) {
    __shared__ __nv_bfloat16 As_hi[128 * KPAD];
    __shared__ __nv_bfloat16 As_lo[128 * KPAD];
    __shared__ __nv_bfloat16 Bt_hi[128 * KPAD];   // transposed: [n][k]
    __shared__ __nv_bfloat16 Bt_lo[128 * KPAD];

    const int tid = threadIdx.x;
    const int lane = tid & 31;
    const int w = tid >> 5;
    const int wm = w >> 1;           // 0..3
    const int wn = w & 1;            // 0..1
    const int g = lane >> 2;         // 0..7
    const int cc = lane & 3;         // 0..3

    const float* Ab = A + (size_t)blockIdx.y * 128 * K;
    const float* Bb = B + (size_t)blockIdx.x * 128;

    const int arow = tid >> 3;          // 0..31
    const int acol = (tid & 7) * 4;     // 0..28
    const int bn = (lane) * 4;          // 0..124 (per-warp contiguous)
    const int bk = w;                   // 0..7

    float4 ra[4], rb[4];

    auto load_gmem = [&](int k0) {
#pragma unroll
        for (int rr = 0; rr < 4; rr++)
            ra[rr] = *(const float4*)(Ab + (size_t)(arow + rr * 32) * K + k0 + acol);
#pragma unroll
        for (int rr = 0; rr < 4; rr++)
            rb[rr] = *(const float4*)(Bb + (size_t)(k0 + bk + rr * 8) * N + bn);
    };

    auto store_smem = [&]() {
#pragma unroll
        for (int rr = 0; rr < 4; rr++) {
            int r = arow + rr * 32;
            uint32_t h0, l0, h1, l1;
            split2pack(ra[rr].x, ra[rr].y, h0, l0);
            split2pack(ra[rr].z, ra[rr].w, h1, l1);
            uint32_t* ph = (uint32_t*)&As_hi[r * KPAD + acol];
            uint32_t* pl = (uint32_t*)&As_lo[r * KPAD + acol];
            ph[0] = h0; ph[1] = h1;
            pl[0] = l0; pl[1] = l1;
        }
#pragma unroll
        for (int rr = 0; rr < 4; rr++) {
            int k = bk + rr * 8;
            float v[4] = {rb[rr].x, rb[rr].y, rb[rr].z, rb[rr].w};
#pragma unroll
            for (int j = 0; j < 4; j++) {
                __nv_bfloat16 h, l;
                split1(v[j], h, l);
                Bt_hi[(bn + j) * KPAD + k] = h;
                Bt_lo[(bn + j) * KPAD + k] = l;
            }
        }
    };

    float acc[2][8][4];
#pragma unroll
    for (int tm = 0; tm < 2; tm++)
#pragma unroll
        for (int tn = 0; tn < 8; tn++)
#pragma unroll
            for (int j = 0; j < 4; j++) acc[tm][tn][j] = 0.f;

    const int ntiles = K / 32;
    load_gmem(0);

    for (int t = 0; t < ntiles; t++) {
        store_smem();
        __syncthreads();
        if (t + 1 < ntiles) load_gmem((t + 1) * 32);

#pragma unroll
        for (int ks = 0; ks < 32; ks += 16) {
            uint32_t ah[2][4], al[2][4];
#pragma unroll
            for (int tm = 0; tm < 2; tm++) {
                int base = (wm * 32 + tm * 16 + g) * KPAD + ks + 2 * cc;
                ah[tm][0] = *(const uint32_t*)&As_hi[base];
                ah[tm][1] = *(const uint32_t*)&As_hi[base + 8 * KPAD];
                ah[tm][2] = *(const uint32_t*)&As_hi[base + 8];
                ah[tm][3] = *(const uint32_t*)&As_hi[base + 8 * KPAD + 8];
                al[tm][0] = *(const uint32_t*)&As_lo[base];
                al[tm][1] = *(const uint32_t*)&As_lo[base + 8 * KPAD];
                al[tm][2] = *(const uint32_t*)&As_lo[base + 8];
                al[tm][3] = *(const uint32_t*)&As_lo[base + 8 * KPAD + 8];
            }
#pragma unroll
            for (int tn = 0; tn < 8; tn++) {
                int bb = (wn * 64 + tn * 8 + g) * KPAD + ks + 2 * cc;
                uint32_t bh[2], bl[2];
                bh[0] = *(const uint32_t*)&Bt_hi[bb];
                bh[1] = *(const uint32_t*)&Bt_hi[bb + 8];
                bl[0] = *(const uint32_t*)&Bt_lo[bb];
                bl[1] = *(const uint32_t*)&Bt_lo[bb + 8];
#pragma unroll
                for (int tm = 0; tm < 2; tm++) {
                    mma16816(acc[tm][tn], ah[tm], bh);
                    mma16816(acc[tm][tn], ah[tm], bl);
                    mma16816(acc[tm][tn], al[tm], bh);
                }
            }
        }
        __syncthreads();
    }

    // epilogue
#pragma unroll
    for (int tm = 0; tm < 2; tm++) {
        int row0 = blockIdx.y * 128 + wm * 32 + tm * 16 + g;
#pragma unroll
        for (int tn = 0; tn < 8; tn++) {
            int col = blockIdx.x * 128 + wn * 64 + tn * 8 + 2 * cc;
            *(float2*)(C + (size_t)row0 * N + col) =
                make_float2(acc[tm][tn][0], acc[tm][tn][1]);
            *(float2*)(C + (size_t)(row0 + 8) * N + col) =
                make_float2(acc[tm][tn][2], acc[tm][tn][3]);
        }
    }
}

// ---------------- RoPE cos/sin table (fp64 for phase accuracy) -------------
__global__ void rope_table(const int* __restrict__ positions) {
    int idx = blockIdx.x * blockDim.x + threadIdx.x;  // t*64 + j
    if (idx >= 2048 * 64) return;
    int t = idx >> 6;
    int j = idx & 63;
    double inv = exp(-(double)j * (log(1.0e6) / 64.0));
    double f = (double)positions[t] * inv;
    g_cos[idx] = (float)cos(f);
    g_sin[idx] = (float)sin(f);
}

// ---------------- fused RMSNorm + RoPE (one warp per token-head) -----------
__global__ void rmsrope(float* __restrict__ X, int nheads, int rowstride,
                        const float* __restrict__ w) {
    int wid = (blockIdx.x * blockDim.x + threadIdx.x) >> 5;
    int lane = threadIdx.x & 31;
    int t = wid / nheads;
    int h = wid - t * nheads;
    if (t >= 2048) return;
    float* x = X + (size_t)t * rowstride + h * 128;

    float v0 = x[lane], v1 = x[lane + 32], v2 = x[lane + 64], v3 = x[lane + 96];
    float ss = v0 * v0 + v1 * v1 + v2 * v2 + v3 * v3;
#pragma unroll
    for (int off = 16; off > 0; off >>= 1) ss += __shfl_xor_sync(0xffffffffu, ss, off);
    float rms = rsqrtf(ss * (1.f / 128.f) + 1e-6f);

    v0 *= rms * w[lane];
    v1 *= rms * w[lane + 32];
    v2 *= rms * w[lane + 64];
    v3 *= rms * w[lane + 96];

    float c0 = g_cos[t * 64 + lane],      s0 = g_sin[t * 64 + lane];
    float c1 = g_cos[t * 64 + lane + 32], s1 = g_sin[t * 64 + lane + 32];

    x[lane]      = v0 * c0 - v2 * s0;
    x[lane + 64] = v2 * c0 + v0 * s0;
    x[lane + 32] = v1 * c1 - v3 * s1;
    x[lane + 96] = v3 * c1 + v1 * s1;
}

// ---------------- causal flash attention -----------------------------------
// grid (32 qblocks, 32 heads), 256 threads. BQ=BKV=64, D=128.
#define ATTN_SMEM_FLOATS (64 * 128 + 128 * 65 + 64 * 132 + 64 * 64)
#define ATTN_SMEM_BYTES (ATTN_SMEM_FLOATS * 4)

__global__ __launch_bounds__(256) void attn_kernel(const float* __restrict__ Q,
                                                   const float* __restrict__ K,
                                                   const float* __restrict__ V,
                                                   float* __restrict__ O) {
    extern __shared__ float sm[];
    float* Qs = sm;                      // 64*128
    float* Kt = Qs + 64 * 128;           // 128*65
    float* Vs = Kt + 128 * 65;           // 64*132
    float* Ps = Vs + 64 * 132;           // 64*64

    const int qb = 31 - blockIdx.x;      // big tiles launch first
    const int h = blockIdx.y;
    const int kvh = h >> 2;              // group = 4
    const int tid = threadIdx.x;
    const int lane = tid & 31;
    const int w = tid >> 5;

    for (int idx = tid; idx < 64 * 128; idx += 256) {
        int r = idx >> 7, d = idx & 127;
        Qs[r * 128 + d] = Q[(size_t)(qb * 64 + r) * 4096 + h * 128 + d];
    }
    __syncthreads();

    float m[8], l[8], acc[8][4];
#pragma unroll
    for (int r = 0; r < 8; r++) {
        m[r] = -1e30f;
        l[r] = 0.f;
#pragma unroll
        for (int j = 0; j < 4; j++) acc[r][j] = 0.f;
    }

    const float scale = 0.08838834764831845f;

    for (int kb = 0; kb <= qb; kb++) {
        for (int idx = tid; idx < 64 * 128; idx += 256) {
            int r = idx >> 7, d = idx & 127;
            size_t gidx = (size_t)(kb * 64 + r) * 1024 + kvh * 128 + d;
            Kt[d * 65 + r] = K[gidx];
            Vs[r * 132 + d] = V[gidx];
        }
        __syncthreads();

#pragma unroll 1
        for (int r = 0; r < 8; r++) {
            const int rg = w * 8 + r;
            const int tq = qb * 64 + rg;
            const float* qrow = Qs + rg * 128;

            float s0 = 0.f, s1 = 0.f;
#pragma unroll 4
            for (int d = 0; d < 128; d++) {
                float qv = qrow[d];
                s0 += qv * Kt[d * 65 + lane];
                s1 += qv * Kt[d * 65 + lane + 32];
            }
            s0 *= scale;
            s1 *= scale;
            if (kb * 64 + lane > tq) s0 = -1e30f;
            if (kb * 64 + lane + 32 > tq) s1 = -1e30f;

            float mx = fmaxf(s0, s1);
#pragma unroll
            for (int off = 16; off > 0; off >>= 1)
                mx = fmaxf(mx, __shfl_xor_sync(0xffffffffu, mx, off));
            float mnew = fmaxf(m[r], mx);
            float p0 = __expf(s0 - mnew);
            float p1 = __expf(s1 - mnew);
            float ps = p0 + p1;
#pragma unroll
            for (int off = 16; off > 0; off >>= 1)
                ps += __shfl_xor_sync(0xffffffffu, ps, off);
            float corr = __expf(m[r] - mnew);
            l[r] = l[r] * corr + ps;
            m[r] = mnew;

            Ps[rg * 64 + lane] = p0;
            Ps[rg * 64 + lane + 32] = p1;
            __syncwarp();

            float4 a = make_float4(acc[r][0] * corr, acc[r][1] * corr,
                                   acc[r][2] * corr, acc[r][3] * corr);
#pragma unroll 4
            for (int k = 0; k < 64; k++) {
                float p = Ps[rg * 64 + k];
                float4 vv = *(const float4*)(Vs + k * 132 + lane * 4);
                a.x += p * vv.x;
                a.y += p * vv.y;
                a.z += p * vv.z;
                a.w += p * vv.w;
            }
            acc[r][0] = a.x; acc[r][1] = a.y; acc[r][2] = a.z; acc[r][3] = a.w;
            __syncwarp();
        }
        __syncthreads();
    }

#pragma unroll
    for (int r = 0; r < 8; r++) {
        int rg = w * 8 + r;
        int tq = qb * 64 + rg;
        float inv = 1.f / l[r];
        float4 o = make_float4(acc[r][0] * inv, acc[r][1] * inv,
                               acc[r][2] * inv, acc[r][3] * inv);
        *(float4*)(O + (size_t)tq * 4096 + h * 128 + lane * 4) = o;
    }
}

// ---------------- launch ----------------------------------------------------
extern "C" void kernel_launch(void* const* d_in, const int* in_sizes, int n_in,
                              void* d_out, int out_size) {
    const float* hidden    = (const float*)d_in[0];
    const int*   positions = (const int*)d_in[1];
    const float* Wq        = (const float*)d_in[2];
    const float* Wk        = (const float*)d_in[3];
    const float* Wv        = (const float*)d_in[4];
    const float* Wo        = (const float*)d_in[5];
    const float* q_norm_w  = (const float*)d_in[6];
    const float* k_norm_w  = (const float*)d_in[7];
    float* out = (float*)d_out;

    float* q;    cudaGetSymbolAddress((void**)&q, g_q);
    float* k;    cudaGetSymbolAddress((void**)&k, g_k);
    float* v;    cudaGetSymbolAddress((void**)&v, g_v);
    float* attn; cudaGetSymbolAddress((void**)&attn, g_attn);

    // QKV projections (tensor cores, split-bf16)
    hgemm_split<<<dim3(32, 16), 256>>>(hidden, Wq, q, 2048, 4096, 4096);
    hgemm_split<<<dim3(8, 16), 256>>>(hidden, Wk, k, 2048, 1024, 4096);
    hgemm_split<<<dim3(8, 16), 256>>>(hidden, Wv, v, 2048, 1024, 4096);

    // RoPE table + fused rmsnorm/rope
    rope_table<<<(2048 * 64 + 255) / 256, 256>>>(positions);
    rmsrope<<<(2048 * 32) / 8, 256>>>(q, 32, 4096, q_norm_w);
    rmsrope<<<(2048 * 8) / 8, 256>>>(k, 8, 1024, k_norm_w);

    // attention
    cudaFuncSetAttribute(attn_kernel, cudaFuncAttributeMaxDynamicSharedMemorySize,
                         ATTN_SMEM_BYTES);
    attn_kernel<<<dim3(32, 32), 256, ATTN_SMEM_BYTES>>>(q, k, v, attn);

    // output projection
    hgemm_split<<<dim3(32, 16), 256>>>(attn, Wo, out, 2048, 4096, 4096);
}

// round 4
// speedup vs baseline: 1.8595x; 1.8595x over previous
#include <cuda_runtime.h>
#include <cuda_bf16.h>
#include <math.h>
#include <stdint.h>

// ---------------- scratch (device globals: no allocation allowed) ----------
__device__ float g_q[2048 * 4096];
__device__ float g_k[2048 * 1024];
__device__ float g_v[2048 * 1024];
__device__ float g_attn[2048 * 4096];
__device__ float g_cos[2048 * 64];
__device__ float g_sin[2048 * 64];

// ==================== split-bf16 tensor-core GEMM (mma.sync) ===============
// C[M,N] = A[M,K] @ B[K,N], fp32 gmem. hi/lo bf16 split, 3 HMMA passes.
// BM=BN=128, BK=32, 256 threads (8 warps 4x2), warp tile 32x64.
// smem layout: X[row][k] bf16, KPAD=40 -> conflict-free loads AND stores.

#define KPAD 40

__device__ __forceinline__ void mma16816(float acc[4], const uint32_t a[4],
                                         const uint32_t b[2]) {
    asm volatile(
        "mma.sync.aligned.m16n8k16.row.col.f32.bf16.bf16.f32 "
        "{%0,%1,%2,%3}, {%4,%5,%6,%7}, {%8,%9}, {%0,%1,%2,%3};\n"
        : "+f"(acc[0]), "+f"(acc[1]), "+f"(acc[2]), "+f"(acc[3])
        : "r"(a[0]), "r"(a[1]), "r"(a[2]), "r"(a[3]), "r"(b[0]), "r"(b[1]));
}

__device__ __forceinline__ void split1(float x, __nv_bfloat16& hi, __nv_bfloat16& lo) {
    hi = __float2bfloat16(x);
    lo = __float2bfloat16(x - __bfloat162float(hi));
}

__device__ __forceinline__ void split2pack(float x, float y, uint32_t& hi, uint32_t& lo) {
    __nv_bfloat16 hx, lx, hy, ly;
    split1(x, hx, lx);
    split1(y, hy, ly);
    hi = ((uint32_t)__bfloat16_as_ushort(hy) << 16) | __bfloat16_as_ushort(hx);
    lo = ((uint32_t)__bfloat16_as_ushort(ly) << 16) | __bfloat16_as_ushort(lx);
}

__global__ __launch_bounds__(256) void hgemm2(const float* __restrict__ A,
                                              const float* __restrict__ B,
                                              float* __restrict__ C,
                                              int M, int N, int K) {
    __shared__ __nv_bfloat16 Ah[128 * KPAD];
    __shared__ __nv_bfloat16 Al[128 * KPAD];
    __shared__ __nv_bfloat16 Bh[128 * KPAD];   // [n][k]
    __shared__ __nv_bfloat16 Bl[128 * KPAD];

    const int tid = threadIdx.x;
    const int lane = tid & 31;
    const int w = tid >> 5;
    const int wm = w >> 1;           // 0..3
    const int wn = w & 1;            // 0..1
    const int g = lane >> 2;         // 0..7
    const int cc = lane & 3;         // 0..3

    const float* Ab = A + (size_t)blockIdx.y * 128 * K;
    const float* Bb = B + (size_t)blockIdx.x * 128;

    // loader mapping: row = (lane>>2) + 8*w (+64*half), kpair = (lane&3) + 4*rr
    const int lrow = (lane >> 2) + 8 * w;     // 0..63
    const int lkp = lane & 3;                 // 0..3

    float2 ra[2][4];        // [half][rr]
    float rb[2][4][2];      // [half][rr][k/k+1]

    auto load_gmem = [&](int k0) {
#pragma unroll
        for (int hf = 0; hf < 2; hf++)
#pragma unroll
            for (int rr = 0; rr < 4; rr++)
                ra[hf][rr] = *(const float2*)(Ab + (size_t)(lrow + 64 * hf) * K +
                                              k0 + 2 * (lkp + 4 * rr));
#pragma unroll
        for (int hf = 0; hf < 2; hf++)
#pragma unroll
            for (int rr = 0; rr < 4; rr++) {
                int krow = k0 + 2 * (lkp + 4 * rr);
                int n = lrow + 64 * hf;
                rb[hf][rr][0] = Bb[(size_t)krow * N + n];
                rb[hf][rr][1] = Bb[(size_t)(krow + 1) * N + n];
            }
    };

    auto store_smem = [&]() {
#pragma unroll
        for (int hf = 0; hf < 2; hf++)
#pragma unroll
            for (int rr = 0; rr < 4; rr++) {
                uint32_t h, l;
                split2pack(ra[hf][rr].x, ra[hf][rr].y, h, l);
                int off = (lrow + 64 * hf) * KPAD + 2 * (lkp + 4 * rr);
                *(uint32_t*)&Ah[off] = h;
                *(uint32_t*)&Al[off] = l;
            }
#pragma unroll
        for (int hf = 0; hf < 2; hf++)
#pragma unroll
            for (int rr = 0; rr < 4; rr++) {
                uint32_t h, l;
                split2pack(rb[hf][rr][0], rb[hf][rr][1], h, l);
                int off = (lrow + 64 * hf) * KPAD + 2 * (lkp + 4 * rr);
                *(uint32_t*)&Bh[off] = h;
                *(uint32_t*)&Bl[off] = l;
            }
    };

    float acc[2][8][4];
#pragma unroll
    for (int tm = 0; tm < 2; tm++)
#pragma unroll
        for (int tn = 0; tn < 8; tn++)
#pragma unroll
            for (int j = 0; j < 4; j++) acc[tm][tn][j] = 0.f;

    const int ntiles = K / 32;
    load_gmem(0);

    for (int t = 0; t < ntiles; t++) {
        store_smem();
        __syncthreads();
        if (t + 1 < ntiles) load_gmem((t + 1) * 32);

#pragma unroll
        for (int ks = 0; ks < 32; ks += 16) {
            uint32_t ah[2][4], al[2][4];
#pragma unroll
            for (int tm = 0; tm < 2; tm++) {
                int base = (wm * 32 + tm * 16 + g) * KPAD + ks + 2 * cc;
                ah[tm][0] = *(const uint32_t*)&Ah[base];
                ah[tm][1] = *(const uint32_t*)&Ah[base + 8 * KPAD];
                ah[tm][2] = *(const uint32_t*)&Ah[base + 8];
                ah[tm][3] = *(const uint32_t*)&Ah[base + 8 * KPAD + 8];
                al[tm][0] = *(const uint32_t*)&Al[base];
                al[tm][1] = *(const uint32_t*)&Al[base + 8 * KPAD];
                al[tm][2] = *(const uint32_t*)&Al[base + 8];
                al[tm][3] = *(const uint32_t*)&Al[base + 8 * KPAD + 8];
            }
#pragma unroll
            for (int tn = 0; tn < 8; tn++) {
                int bb = (wn * 64 + tn * 8 + g) * KPAD + ks + 2 * cc;
                uint32_t bh[2], bl[2];
                bh[0] = *(const uint32_t*)&Bh[bb];
                bh[1] = *(const uint32_t*)&Bh[bb + 8];
                bl[0] = *(const uint32_t*)&Bl[bb];
                bl[1] = *(const uint32_t*)&Bl[bb + 8];
#pragma unroll
                for (int tm = 0; tm < 2; tm++) {
                    mma16816(acc[tm][tn], ah[tm], bh);
                    mma16816(acc[tm][tn], ah[tm], bl);
                    mma16816(acc[tm][tn], al[tm], bh);
                }
            }
        }
        __syncthreads();
    }

    // epilogue
#pragma unroll
    for (int tm = 0; tm < 2; tm++) {
        int row0 = blockIdx.y * 128 + wm * 32 + tm * 16 + g;
#pragma unroll
        for (int tn = 0; tn < 8; tn++) {
            int col = blockIdx.x * 128 + wn * 64 + tn * 8 + 2 * cc;
            *(float2*)(C + (size_t)row0 * N + col) =
                make_float2(acc[tm][tn][0], acc[tm][tn][1]);
            *(float2*)(C + (size_t)(row0 + 8) * N + col) =
                make_float2(acc[tm][tn][2], acc[tm][tn][3]);
        }
    }
}

// ---------------- RoPE cos/sin table (fp64 for phase accuracy) -------------
__global__ void rope_table(const int* __restrict__ positions) {
    int idx = blockIdx.x * blockDim.x + threadIdx.x;
    if (idx >= 2048 * 64) return;
    int t = idx >> 6;
    int j = idx & 63;
    double inv = exp(-(double)j * (log(1.0e6) / 64.0));
    double f = (double)positions[t] * inv;
    g_cos[idx] = (float)cos(f);
    g_sin[idx] = (float)sin(f);
}

// ---------------- fused RMSNorm + RoPE for Q and K in one launch -----------
__global__ void rmsrope_both(float* __restrict__ Q, float* __restrict__ K,
                             const float* __restrict__ qw,
                             const float* __restrict__ kw) {
    int wg = (blockIdx.x * blockDim.x + threadIdx.x) >> 5;
    int lane = threadIdx.x & 31;

    float* x;
    int t;
    const float* w;
    if (wg < 2048 * 32) {
        t = wg >> 5;
        int h = wg & 31;
        x = Q + (size_t)t * 4096 + h * 128;
        w = qw;
    } else {
        int wg2 = wg - 2048 * 32;
        if (wg2 >= 2048 * 8) return;
        t = wg2 >> 3;
        int h = wg2 & 7;
        x = K + (size_t)t * 1024 + h * 128;
        w = kw;
    }

    float v0 = x[lane], v1 = x[lane + 32], v2 = x[lane + 64], v3 = x[lane + 96];
    float ss = v0 * v0 + v1 * v1 + v2 * v2 + v3 * v3;
#pragma unroll
    for (int off = 16; off > 0; off >>= 1) ss += __shfl_xor_sync(0xffffffffu, ss, off);
    float rms = rsqrtf(ss * (1.f / 128.f) + 1e-6f);

    v0 *= rms * w[lane];
    v1 *= rms * w[lane + 32];
    v2 *= rms * w[lane + 64];
    v3 *= rms * w[lane + 96];

    float c0 = g_cos[t * 64 + lane],      s0 = g_sin[t * 64 + lane];
    float c1 = g_cos[t * 64 + lane + 32], s1 = g_sin[t * 64 + lane + 32];

    x[lane]      = v0 * c0 - v2 * s0;
    x[lane + 64] = v2 * c0 + v0 * s0;
    x[lane + 32] = v1 * c1 - v3 * s1;
    x[lane + 96] = v3 * c1 + v1 * s1;
}

// ---------------- causal flash attention (LDS-amortized) -------------------
// grid (32 qblocks, 32 heads), 256 threads. BQ=BKV=64, D=128.
#define ATTN_SMEM_FLOATS (64 * 128 + 128 * 65 + 64 * 132 + 64 * 64)
#define ATTN_SMEM_BYTES (ATTN_SMEM_FLOATS * 4)

__global__ __launch_bounds__(256) void attn_kernel(const float* __restrict__ Q,
                                                   const float* __restrict__ K,
                                                   const float* __restrict__ V,
                                                   float* __restrict__ O) {
    extern __shared__ float sm[];
    float* Qs = sm;                      // 64*128
    float* Kt = Qs + 64 * 128;           // 128*65 (transposed)
    float* Vs = Kt + 128 * 65;           // 64*132
    float* Ps = Vs + 64 * 132;           // 64*64

    const int qb = 31 - blockIdx.x;
    const int h = blockIdx.y;
    const int kvh = h >> 2;
    const int tid = threadIdx.x;
    const int lane = tid & 31;
    const int w = tid >> 5;

    for (int idx = tid; idx < 64 * 128; idx += 256) {
        int r = idx >> 7, d = idx & 127;
        Qs[r * 128 + d] = Q[(size_t)(qb * 64 + r) * 4096 + h * 128 + d];
    }
    __syncthreads();

    float m[8], l[8], acc[8][4];
#pragma unroll
    for (int r = 0; r < 8; r++) {
        m[r] = -1e30f;
        l[r] = 0.f;
#pragma unroll
        for (int j = 0; j < 4; j++) acc[r][j] = 0.f;
    }

    const float scale = 0.08838834764831845f;

    for (int kb = 0; kb <= qb; kb++) {
        for (int idx = tid; idx < 64 * 128; idx += 256) {
            int r = idx >> 7, d = idx & 127;
            size_t gidx = (size_t)(kb * 64 + r) * 1024 + kvh * 128 + d;
            Kt[d * 65 + r] = K[gidx];
            Vs[r * 132 + d] = V[gidx];
        }
        __syncthreads();

        // ---- scores: all 8 rows at once, sharing K loads ----
        float s[8][2];
#pragma unroll
        for (int r = 0; r < 8; r++) s[r][0] = s[r][1] = 0.f;

        const float* qbase = Qs + (w * 8) * 128;
#pragma unroll 4
        for (int d = 0; d < 128; d++) {
            float k0 = Kt[d * 65 + lane];
            float k1 = Kt[d * 65 + lane + 32];
#pragma unroll
            for (int r = 0; r < 8; r++) {
                float qv = qbase[r * 128 + d];
                s[r][0] += qv * k0;
                s[r][1] += qv * k1;
            }
        }

        // ---- softmax per row ----
        float corr[8];
#pragma unroll
        for (int r = 0; r < 8; r++) {
            const int tq = qb * 64 + w * 8 + r;
            float s0 = s[r][0] * scale;
            float s1 = s[r][1] * scale;
            if (kb * 64 + lane > tq) s0 = -1e30f;
            if (kb * 64 + lane + 32 > tq) s1 = -1e30f;

            float mx = fmaxf(s0, s1);
#pragma unroll
            for (int off = 16; off > 0; off >>= 1)
                mx = fmaxf(mx, __shfl_xor_sync(0xffffffffu, mx, off));
            float mnew = fmaxf(m[r], mx);
            float p0 = __expf(s0 - mnew);
            float p1 = __expf(s1 - mnew);
            float ps = p0 + p1;
#pragma unroll
            for (int off = 16; off > 0; off >>= 1)
                ps += __shfl_xor_sync(0xffffffffu, ps, off);
            corr[r] = __expf(m[r] - mnew);
            l[r] = l[r] * corr[r] + ps;
            m[r] = mnew;

            Ps[(w * 8 + r) * 64 + lane] = p0;
            Ps[(w * 8 + r) * 64 + lane + 32] = p1;
        }
        __syncwarp();

#pragma unroll
        for (int r = 0; r < 8; r++) {
            acc[r][0] *= corr[r];
            acc[r][1] *= corr[r];
            acc[r][2] *= corr[r];
            acc[r][3] *= corr[r];
        }

        // ---- PV: share V loads across 8 rows ----
        const float* pbase = Ps + (w * 8) * 64;
#pragma unroll 2
        for (int k = 0; k < 64; k++) {
            float4 vv = *(const float4*)(Vs + k * 132 + lane * 4);
#pragma unroll
            for (int r = 0; r < 8; r++) {
                float p = pbase[r * 64 + k];
                acc[r][0] += p * vv.x;
                acc[r][1] += p * vv.y;
                acc[r][2] += p * vv.z;
                acc[r][3] += p * vv.w;
            }
        }
        __syncthreads();
    }

#pragma unroll
    for (int r = 0; r < 8; r++) {
        int tq = qb * 64 + w * 8 + r;
        float inv = 1.f / l[r];
        float4 o = make_float4(acc[r][0] * inv, acc[r][1] * inv,
                               acc[r][2] * inv, acc[r][3] * inv);
        *(float4*)(O + (size_t)tq * 4096 + h * 128 + lane * 4) = o;
    }
}

// ---------------- launch ----------------------------------------------------
extern "C" void kernel_launch(void* const* d_in, const int* in_sizes, int n_in,
                              void* d_out, int out_size) {
    const float* hidden    = (const float*)d_in[0];
    const int*   positions = (const int*)d_in[1];
    const float* Wq        = (const float*)d_in[2];
    const float* Wk        = (const float*)d_in[3];
    const float* Wv        = (const float*)d_in[4];
    const float* Wo        = (const float*)d_in[5];
    const float* q_norm_w  = (const float*)d_in[6];
    const float* k_norm_w  = (const float*)d_in[7];
    float* out = (float*)d_out;

    float* q;    cudaGetSymbolAddress((void**)&q, g_q);
    float* k;    cudaGetSymbolAddress((void**)&k, g_k);
    float* v;    cudaGetSymbolAddress((void**)&v, g_v);
    float* attn; cudaGetSymbolAddress((void**)&attn, g_attn);

    cudaFuncSetAttribute(attn_kernel, cudaFuncAttributeMaxDynamicSharedMemorySize,
                         ATTN_SMEM_BYTES);

    // 1: rope table
    rope_table<<<(2048 * 64 + 255) / 256, 256>>>(positions);

    // 2-4: QKV projections
    hgemm2<<<dim3(32, 16), 256>>>(hidden, Wq, q, 2048, 4096, 4096);
    hgemm2<<<dim3(8, 16), 256>>>(hidden, Wk, k, 2048, 1024, 4096);
    hgemm2<<<dim3(8, 16), 256>>>(hidden, Wv, v, 2048, 1024, 4096);

    // 5: fused rmsnorm+rope
    rmsrope_both<<<(2048 * 40) / 8, 256>>>(q, k, q_norm_w, k_norm_w);

    // 6: attention
    attn_kernel<<<dim3(32, 32), 256, ATTN_SMEM_BYTES>>>(q, k, v, attn);

    // 7: output projection
    hgemm2<<<dim3(32, 16), 256>>>(attn, Wo, out, 2048, 4096, 4096);
}

// round 5
// speedup vs baseline: 2.0579x; 1.1067x over previous
#include <cuda_runtime.h>
#include <cuda_bf16.h>
#include <math.h>
#include <stdint.h>

// ---------------- scratch (device globals: no allocation allowed) ----------
__device__ float g_q[2048 * 4096];
__device__ float g_k[2048 * 1024];
__device__ float g_v[2048 * 1024];
__device__ float g_attn[2048 * 4096];
__device__ float g_cos[2048 * 64];
__device__ float g_sin[2048 * 64];

// ==================== split-bf16 tensor-core GEMM (mma.sync) ===============
// C[M,N] = A[M,K] @ B[K,N], fp32 gmem. hi/lo bf16 split, 3 HMMA passes.
// BM=BN=128, BK=32, 256 threads (8 warps 4x2), warp tile 32x64.
// Double-buffered dynamic smem; ldmatrix fragment loads; KPAD=40 rows
// (80B stride) -> conflict-free for STS.32, LDS and LDSM.

#define KPAD 40
#define TILE_HALFS (128 * KPAD)            // bf16 elems per matrix per buffer
#define BUF_HALFS (4 * TILE_HALFS)         // Ah, Al, Bh, Bl
#define GEMM_SMEM_BYTES (2 * BUF_HALFS * 2)

__device__ __forceinline__ void mma16816(float acc[4], const uint32_t a[4],
                                         const uint32_t b[2]) {
    asm volatile(
        "mma.sync.aligned.m16n8k16.row.col.f32.bf16.bf16.f32 "
        "{%0,%1,%2,%3}, {%4,%5,%6,%7}, {%8,%9}, {%0,%1,%2,%3};\n"
        : "+f"(acc[0]), "+f"(acc[1]), "+f"(acc[2]), "+f"(acc[3])
        : "r"(a[0]), "r"(a[1]), "r"(a[2]), "r"(a[3]), "r"(b[0]), "r"(b[1]));
}

__device__ __forceinline__ void ldsm_x4(uint32_t& r0, uint32_t& r1,
                                        uint32_t& r2, uint32_t& r3,
                                        uint32_t addr) {
    asm volatile(
        "ldmatrix.sync.aligned.m8n8.x4.shared.b16 {%0,%1,%2,%3}, [%4];"
        : "=r"(r0), "=r"(r1), "=r"(r2), "=r"(r3) : "r"(addr));
}

__device__ __forceinline__ uint32_t smem_u32(const void* p) {
    uint32_t a;
    asm("{ .reg .u64 t; cvta.to.shared.u64 t, %1; cvt.u32.u64 %0, t; }"
        : "=r"(a) : "l"(p));
    return a;
}

__device__ __forceinline__ void split1(float x, __nv_bfloat16& hi, __nv_bfloat16& lo) {
    hi = __float2bfloat16(x);
    lo = __float2bfloat16(x - __bfloat162float(hi));
}

__device__ __forceinline__ void split2pack(float x, float y, uint32_t& hi, uint32_t& lo) {
    __nv_bfloat16 hx, lx, hy, ly;
    split1(x, hx, lx);
    split1(y, hy, ly);
    hi = ((uint32_t)__bfloat16_as_ushort(hy) << 16) | __bfloat16_as_ushort(hx);
    lo = ((uint32_t)__bfloat16_as_ushort(ly) << 16) | __bfloat16_as_ushort(lx);
}

__global__ __launch_bounds__(256) void hgemm2(const float* __restrict__ A,
                                              const float* __restrict__ B,
                                              float* __restrict__ C,
                                              int M, int N, int K) {
    extern __shared__ __nv_bfloat16 smbuf[];

    const int tid = threadIdx.x;
    const int lane = tid & 31;
    const int w = tid >> 5;
    const int wm = w >> 1;           // 0..3
    const int wn = w & 1;            // 0..1
    const int g = lane >> 2;         // 0..7
    const int cc = lane & 3;         // 0..3
    const int quad = lane >> 3;      // 0..3
    const int qr = lane & 7;         // 0..7

    const float* Ab = A + (size_t)blockIdx.y * 128 * K;
    const float* Bb = B + (size_t)blockIdx.x * 128;

    // loader mapping: row = (lane>>2) + 8*w (+64*half), kpair = (lane&3) + 4*rr
    const int lrow = (lane >> 2) + 8 * w;
    const int lkp = lane & 3;

    const uint32_t smbase = smem_u32(smbuf);

    float2 ra[2][4];
    float rb[2][4][2];

    auto load_gmem = [&](int k0) {
#pragma unroll
        for (int hf = 0; hf < 2; hf++)
#pragma unroll
            for (int rr = 0; rr < 4; rr++)
                ra[hf][rr] = *(const float2*)(Ab + (size_t)(lrow + 64 * hf) * K +
                                              k0 + 2 * (lkp + 4 * rr));
#pragma unroll
        for (int hf = 0; hf < 2; hf++)
#pragma unroll
            for (int rr = 0; rr < 4; rr++) {
                int krow = k0 + 2 * (lkp + 4 * rr);
                int n = lrow + 64 * hf;
                rb[hf][rr][0] = Bb[(size_t)krow * N + n];
                rb[hf][rr][1] = Bb[(size_t)(krow + 1) * N + n];
            }
    };

    auto store_smem = [&](int buf) {
        __nv_bfloat16* Ah = smbuf + buf * BUF_HALFS;
        __nv_bfloat16* Al = Ah + TILE_HALFS;
        __nv_bfloat16* Bh = Ah + 2 * TILE_HALFS;
        __nv_bfloat16* Bl = Ah + 3 * TILE_HALFS;
#pragma unroll
        for (int hf = 0; hf < 2; hf++)
#pragma unroll
            for (int rr = 0; rr < 4; rr++) {
                uint32_t h, l;
                split2pack(ra[hf][rr].x, ra[hf][rr].y, h, l);
                int off = (lrow + 64 * hf) * KPAD + 2 * (lkp + 4 * rr);
                *(uint32_t*)&Ah[off] = h;
                *(uint32_t*)&Al[off] = l;
            }
#pragma unroll
        for (int hf = 0; hf < 2; hf++)
#pragma unroll
            for (int rr = 0; rr < 4; rr++) {
                uint32_t h, l;
                split2pack(rb[hf][rr][0], rb[hf][rr][1], h, l);
                int off = (lrow + 64 * hf) * KPAD + 2 * (lkp + 4 * rr);
                *(uint32_t*)&Bh[off] = h;
                *(uint32_t*)&Bl[off] = l;
            }
    };

    float acc[2][8][4];
#pragma unroll
    for (int tm = 0; tm < 2; tm++)
#pragma unroll
        for (int tn = 0; tn < 8; tn++)
#pragma unroll
            for (int j = 0; j < 4; j++) acc[tm][tn][j] = 0.f;

    // ldmatrix lane-address components (byte offsets; 2B per elem).
    // A tiles: quad0: (row qr, ks), quad1: (row 8+qr, ks),
    //          quad2: (row qr, ks+8), quad3: (row 8+qr, ks+8)
    const uint32_t aLaneOff =
        (uint32_t)((wm * 32 + (quad & 1) * 8 + qr) * KPAD + (quad >> 1) * 8) * 2;
    // B tiles: quad0: (n qr, ks), quad1: (n qr, ks+8),
    //          quad2: (n 8+qr, ks), quad3: (n 8+qr, ks+8)
    const uint32_t bLaneOff =
        (uint32_t)((wn * 64 + (quad >> 1) * 8 + qr) * KPAD + (quad & 1) * 8) * 2;

    auto mma_tile = [&](int buf) {
        const uint32_t sAh = smbase + buf * BUF_HALFS * 2;
        const uint32_t sAl = sAh + TILE_HALFS * 2;
        const uint32_t sBh = sAh + 2 * TILE_HALFS * 2;
        const uint32_t sBl = sAh + 3 * TILE_HALFS * 2;
#pragma unroll
        for (int ks = 0; ks < 32; ks += 16) {
            uint32_t ah[2][4], al[2][4];
#pragma unroll
            for (int tm = 0; tm < 2; tm++) {
                uint32_t off = aLaneOff + (uint32_t)(tm * 16 * KPAD + ks) * 2;
                ldsm_x4(ah[tm][0], ah[tm][1], ah[tm][2], ah[tm][3], sAh + off);
                ldsm_x4(al[tm][0], al[tm][1], al[tm][2], al[tm][3], sAl + off);
            }
#pragma unroll
            for (int tp = 0; tp < 4; tp++) {
                uint32_t off = bLaneOff + (uint32_t)(tp * 16 * KPAD + ks) * 2;
                uint32_t bh[4], bl[4];
                ldsm_x4(bh[0], bh[1], bh[2], bh[3], sBh + off);
                ldsm_x4(bl[0], bl[1], bl[2], bl[3], sBl + off);
#pragma unroll
                for (int half = 0; half < 2; half++) {
                    const int tn = tp * 2 + half;
#pragma unroll
                    for (int tm = 0; tm < 2; tm++) {
                        mma16816(acc[tm][tn], ah[tm], &bh[half * 2]);
                        mma16816(acc[tm][tn], ah[tm], &bl[half * 2]);
                        mma16816(acc[tm][tn], al[tm], &bh[half * 2]);
                    }
                }
            }
        }
    };

    const int ntiles = K / 32;

    load_gmem(0);
    store_smem(0);
    load_gmem(32);
    __syncthreads();

    for (int t = 0; t < ntiles; t++) {
        mma_tile(t & 1);
        if (t + 1 < ntiles) {
            store_smem((t + 1) & 1);
            if (t + 2 < ntiles) load_gmem((t + 2) * 32);
        }
        __syncthreads();
    }

    // epilogue
#pragma unroll
    for (int tm = 0; tm < 2; tm++) {
        int row0 = blockIdx.y * 128 + wm * 32 + tm * 16 + g;
#pragma unroll
        for (int tn = 0; tn < 8; tn++) {
            int col = blockIdx.x * 128 + wn * 64 + tn * 8 + 2 * cc;
            *(float2*)(C + (size_t)row0 * N + col) =
                make_float2(acc[tm][tn][0], acc[tm][tn][1]);
            *(float2*)(C + (size_t)(row0 + 8) * N + col) =
                make_float2(acc[tm][tn][2], acc[tm][tn][3]);
        }
    }
}

// ---------------- RoPE cos/sin table (fp64 for phase accuracy) -------------
__global__ void rope_table(const int* __restrict__ positions) {
    int idx = blockIdx.x * blockDim.x + threadIdx.x;
    if (idx >= 2048 * 64) return;
    int t = idx >> 6;
    int j = idx & 63;
    double inv = exp(-(double)j * (log(1.0e6) / 64.0));
    double f = (double)positions[t] * inv;
    g_cos[idx] = (float)cos(f);
    g_sin[idx] = (float)sin(f);
}

// ---------------- fused RMSNorm + RoPE for Q and K in one launch -----------
__global__ void rmsrope_both(float* __restrict__ Q, float* __restrict__ K,
                             const float* __restrict__ qw,
                             const float* __restrict__ kw) {
    int wg = (blockIdx.x * blockDim.x + threadIdx.x) >> 5;
    int lane = threadIdx.x & 31;

    float* x;
    int t;
    const float* w;
    if (wg < 2048 * 32) {
        t = wg >> 5;
        int h = wg & 31;
        x = Q + (size_t)t * 4096 + h * 128;
        w = qw;
    } else {
        int wg2 = wg - 2048 * 32;
        if (wg2 >= 2048 * 8) return;
        t = wg2 >> 3;
        int h = wg2 & 7;
        x = K + (size_t)t * 1024 + h * 128;
        w = kw;
    }

    float v0 = x[lane], v1 = x[lane + 32], v2 = x[lane + 64], v3 = x[lane + 96];
    float ss = v0 * v0 + v1 * v1 + v2 * v2 + v3 * v3;
#pragma unroll
    for (int off = 16; off > 0; off >>= 1) ss += __shfl_xor_sync(0xffffffffu, ss, off);
    float rms = rsqrtf(ss * (1.f / 128.f) + 1e-6f);

    v0 *= rms * w[lane];
    v1 *= rms * w[lane + 32];
    v2 *= rms * w[lane + 64];
    v3 *= rms * w[lane + 96];

    float c0 = g_cos[t * 64 + lane],      s0 = g_sin[t * 64 + lane];
    float c1 = g_cos[t * 64 + lane + 32], s1 = g_sin[t * 64 + lane + 32];

    x[lane]      = v0 * c0 - v2 * s0;
    x[lane + 64] = v2 * c0 + v0 * s0;
    x[lane + 32] = v1 * c1 - v3 * s1;
    x[lane + 96] = v3 * c1 + v1 * s1;
}

// ---------------- causal flash attention (LDS-amortized) -------------------
#define ATTN_SMEM_FLOATS (64 * 128 + 128 * 65 + 64 * 132 + 64 * 64)
#define ATTN_SMEM_BYTES (ATTN_SMEM_FLOATS * 4)

__global__ __launch_bounds__(256) void attn_kernel(const float* __restrict__ Q,
                                                   const float* __restrict__ K,
                                                   const float* __restrict__ V,
                                                   float* __restrict__ O) {
    extern __shared__ float sm[];
    float* Qs = sm;
    float* Kt = Qs + 64 * 128;
    float* Vs = Kt + 128 * 65;
    float* Ps = Vs + 64 * 132;

    const int qb = 31 - blockIdx.x;
    const int h = blockIdx.y;
    const int kvh = h >> 2;
    const int tid = threadIdx.x;
    const int lane = tid & 31;
    const int w = tid >> 5;

    for (int idx = tid; idx < 64 * 128; idx += 256) {
        int r = idx >> 7, d = idx & 127;
        Qs[r * 128 + d] = Q[(size_t)(qb * 64 + r) * 4096 + h * 128 + d];
    }
    __syncthreads();

    float m[8], l[8], acc[8][4];
#pragma unroll
    for (int r = 0; r < 8; r++) {
        m[r] = -1e30f;
        l[r] = 0.f;
#pragma unroll
        for (int j = 0; j < 4; j++) acc[r][j] = 0.f;
    }

    const float scale = 0.08838834764831845f;

    for (int kb = 0; kb <= qb; kb++) {
        for (int idx = tid; idx < 64 * 128; idx += 256) {
            int r = idx >> 7, d = idx & 127;
            size_t gidx = (size_t)(kb * 64 + r) * 1024 + kvh * 128 + d;
            Kt[d * 65 + r] = K[gidx];
            Vs[r * 132 + d] = V[gidx];
        }
        __syncthreads();

        float s[8][2];
#pragma unroll
        for (int r = 0; r < 8; r++) s[r][0] = s[r][1] = 0.f;

        const float* qbase = Qs + (w * 8) * 128;
#pragma unroll 4
        for (int d = 0; d < 128; d++) {
            float k0 = Kt[d * 65 + lane];
            float k1 = Kt[d * 65 + lane + 32];
#pragma unroll
            for (int r = 0; r < 8; r++) {
                float qv = qbase[r * 128 + d];
                s[r][0] += qv * k0;
                s[r][1] += qv * k1;
            }
        }

        float corr[8];
#pragma unroll
        for (int r = 0; r < 8; r++) {
            const int tq = qb * 64 + w * 8 + r;
            float s0 = s[r][0] * scale;
            float s1 = s[r][1] * scale;
            if (kb * 64 + lane > tq) s0 = -1e30f;
            if (kb * 64 + lane + 32 > tq) s1 = -1e30f;

            float mx = fmaxf(s0, s1);
#pragma unroll
            for (int off = 16; off > 0; off >>= 1)
                mx = fmaxf(mx, __shfl_xor_sync(0xffffffffu, mx, off));
            float mnew = fmaxf(m[r], mx);
            float p0 = __expf(s0 - mnew);
            float p1 = __expf(s1 - mnew);
            float ps = p0 + p1;
#pragma unroll
            for (int off = 16; off > 0; off >>= 1)
                ps += __shfl_xor_sync(0xffffffffu, ps, off);
            corr[r] = __expf(m[r] - mnew);
            l[r] = l[r] * corr[r] + ps;
            m[r] = mnew;

            Ps[(w * 8 + r) * 64 + lane] = p0;
            Ps[(w * 8 + r) * 64 + lane + 32] = p1;
        }
        __syncwarp();

#pragma unroll
        for (int r = 0; r < 8; r++) {
            acc[r][0] *= corr[r];
            acc[r][1] *= corr[r];
            acc[r][2] *= corr[r];
            acc[r][3] *= corr[r];
        }

        const float* pbase = Ps + (w * 8) * 64;
#pragma unroll 2
        for (int k = 0; k < 64; k++) {
            float4 vv = *(const float4*)(Vs + k * 132 + lane * 4);
#pragma unroll
            for (int r = 0; r < 8; r++) {
                float p = pbase[r * 64 + k];
                acc[r][0] += p * vv.x;
                acc[r][1] += p * vv.y;
                acc[r][2] += p * vv.z;
                acc[r][3] += p * vv.w;
            }
        }
        __syncthreads();
    }

#pragma unroll
    for (int r = 0; r < 8; r++) {
        int tq = qb * 64 + w * 8 + r;
        float inv = 1.f / l[r];
        float4 o = make_float4(acc[r][0] * inv, acc[r][1] * inv,
                               acc[r][2] * inv, acc[r][3] * inv);
        *(float4*)(O + (size_t)tq * 4096 + h * 128 + lane * 4) = o;
    }
}

// ---------------- launch ----------------------------------------------------
extern "C" void kernel_launch(void* const* d_in, const int* in_sizes, int n_in,
                              void* d_out, int out_size) {
    const float* hidden    = (const float*)d_in[0];
    const int*   positions = (const int*)d_in[1];
    const float* Wq        = (const float*)d_in[2];
    const float* Wk        = (const float*)d_in[3];
    const float* Wv        = (const float*)d_in[4];
    const float* Wo        = (const float*)d_in[5];
    const float* q_norm_w  = (const float*)d_in[6];
    const float* k_norm_w  = (const float*)d_in[7];
    float* out = (float*)d_out;

    float* q;    cudaGetSymbolAddress((void**)&q, g_q);
    float* k;    cudaGetSymbolAddress((void**)&k, g_k);
    float* v;    cudaGetSymbolAddress((void**)&v, g_v);
    float* attn; cudaGetSymbolAddress((void**)&attn, g_attn);

    cudaFuncSetAttribute(hgemm2, cudaFuncAttributeMaxDynamicSharedMemorySize,
                         GEMM_SMEM_BYTES);
    cudaFuncSetAttribute(attn_kernel, cudaFuncAttributeMaxDynamicSharedMemorySize,
                         ATTN_SMEM_BYTES);

    // 1: rope table
    rope_table<<<(2048 * 64 + 255) / 256, 256>>>(positions);

    // 2-4: QKV projections
    hgemm2<<<dim3(32, 16), 256, GEMM_SMEM_BYTES>>>(hidden, Wq, q, 2048, 4096, 4096);
    hgemm2<<<dim3(8, 16), 256, GEMM_SMEM_BYTES>>>(hidden, Wk, k, 2048, 1024, 4096);
    hgemm2<<<dim3(8, 16), 256, GEMM_SMEM_BYTES>>>(hidden, Wv, v, 2048, 1024, 4096);

    // 5: fused rmsnorm+rope
    rmsrope_both<<<(2048 * 40) / 8, 256>>>(q, k, q_norm_w, k_norm_w);

    // 6: attention
    attn_kernel<<<dim3(32, 32), 256, ATTN_SMEM_BYTES>>>(q, k, v, attn);

    // 7: output projection
    hgemm2<<<dim3(32, 16), 256, GEMM_SMEM_BYTES>>>(attn, Wo, out, 2048, 4096, 4096);
}

// round 6
// speedup vs baseline: 2.7075x; 1.3157x over previous
#include <cuda_runtime.h>
#include <cuda_bf16.h>
#include <math.h>
#include <stdint.h>

// ---------------- scratch (device globals: no allocation allowed) ----------
__device__ float g_q[2048 * 4096];
__device__ float g_k[2048 * 1024];
__device__ float g_v[2048 * 1024];
__device__ float g_attn[2048 * 4096];
__device__ float g_cos[2048 * 64];
__device__ float g_sin[2048 * 64];

// ==================== shared helpers =======================================
__device__ __forceinline__ void mma16816(float acc[4], const uint32_t a[4],
                                         const uint32_t b[2]) {
    asm volatile(
        "mma.sync.aligned.m16n8k16.row.col.f32.bf16.bf16.f32 "
        "{%0,%1,%2,%3}, {%4,%5,%6,%7}, {%8,%9}, {%0,%1,%2,%3};\n"
        : "+f"(acc[0]), "+f"(acc[1]), "+f"(acc[2]), "+f"(acc[3])
        : "r"(a[0]), "r"(a[1]), "r"(a[2]), "r"(a[3]), "r"(b[0]), "r"(b[1]));
}

__device__ __forceinline__ void ldsm_x4(uint32_t& r0, uint32_t& r1,
                                        uint32_t& r2, uint32_t& r3,
                                        uint32_t addr) {
    asm volatile(
        "ldmatrix.sync.aligned.m8n8.x4.shared.b16 {%0,%1,%2,%3}, [%4];"
        : "=r"(r0), "=r"(r1), "=r"(r2), "=r"(r3) : "r"(addr));
}

__device__ __forceinline__ uint32_t smem_u32(const void* p) {
    uint32_t a;
    asm("{ .reg .u64 t; cvta.to.shared.u64 t, %1; cvt.u32.u64 %0, t; }"
        : "=r"(a) : "l"(p));
    return a;
}

__device__ __forceinline__ void split1(float x, __nv_bfloat16& hi, __nv_bfloat16& lo) {
    hi = __float2bfloat16(x);
    lo = __float2bfloat16(x - __bfloat162float(hi));
}

__device__ __forceinline__ void split2pack(float x, float y, uint32_t& hi, uint32_t& lo) {
    __nv_bfloat16 hx, lx, hy, ly;
    split1(x, hx, lx);
    split1(y, hy, ly);
    hi = ((uint32_t)__bfloat16_as_ushort(hy) << 16) | __bfloat16_as_ushort(hx);
    lo = ((uint32_t)__bfloat16_as_ushort(ly) << 16) | __bfloat16_as_ushort(lx);
}

// ==================== split-bf16 tensor-core GEMM (mma.sync) ===============
#define KPAD 40
#define TILE_HALFS (128 * KPAD)
#define BUF_HALFS (4 * TILE_HALFS)
#define GEMM_SMEM_BYTES (2 * BUF_HALFS * 2)

__global__ __launch_bounds__(256) void hgemm2(const float* __restrict__ A,
                                              const float* __restrict__ B,
                                              float* __restrict__ C,
                                              int M, int N, int K) {
    extern __shared__ __nv_bfloat16 smbuf[];

    const int tid = threadIdx.x;
    const int lane = tid & 31;
    const int w = tid >> 5;
    const int wm = w >> 1;
    const int wn = w & 1;
    const int g = lane >> 2;
    const int cc = lane & 3;
    const int quad = lane >> 3;
    const int qr = lane & 7;

    const float* Ab = A + (size_t)blockIdx.y * 128 * K;
    const float* Bb = B + (size_t)blockIdx.x * 128;

    const int lrow = (lane >> 2) + 8 * w;
    const int lkp = lane & 3;

    const uint32_t smbase = smem_u32(smbuf);

    float2 ra[2][4];
    float rb[2][4][2];

    auto load_gmem = [&](int k0) {
#pragma unroll
        for (int hf = 0; hf < 2; hf++)
#pragma unroll
            for (int rr = 0; rr < 4; rr++)
                ra[hf][rr] = *(const float2*)(Ab + (size_t)(lrow + 64 * hf) * K +
                                              k0 + 2 * (lkp + 4 * rr));
#pragma unroll
        for (int hf = 0; hf < 2; hf++)
#pragma unroll
            for (int rr = 0; rr < 4; rr++) {
                int krow = k0 + 2 * (lkp + 4 * rr);
                int n = lrow + 64 * hf;
                rb[hf][rr][0] = Bb[(size_t)krow * N + n];
                rb[hf][rr][1] = Bb[(size_t)(krow + 1) * N + n];
            }
    };

    auto store_smem = [&](int buf) {
        __nv_bfloat16* Ah = smbuf + buf * BUF_HALFS;
        __nv_bfloat16* Al = Ah + TILE_HALFS;
        __nv_bfloat16* Bh = Ah + 2 * TILE_HALFS;
        __nv_bfloat16* Bl = Ah + 3 * TILE_HALFS;
#pragma unroll
        for (int hf = 0; hf < 2; hf++)
#pragma unroll
            for (int rr = 0; rr < 4; rr++) {
                uint32_t h, l;
                split2pack(ra[hf][rr].x, ra[hf][rr].y, h, l);
                int off = (lrow + 64 * hf) * KPAD + 2 * (lkp + 4 * rr);
                *(uint32_t*)&Ah[off] = h;
                *(uint32_t*)&Al[off] = l;
            }
#pragma unroll
        for (int hf = 0; hf < 2; hf++)
#pragma unroll
            for (int rr = 0; rr < 4; rr++) {
                uint32_t h, l;
                split2pack(rb[hf][rr][0], rb[hf][rr][1], h, l);
                int off = (lrow + 64 * hf) * KPAD + 2 * (lkp + 4 * rr);
                *(uint32_t*)&Bh[off] = h;
                *(uint32_t*)&Bl[off] = l;
            }
    };

    float acc[2][8][4];
#pragma unroll
    for (int tm = 0; tm < 2; tm++)
#pragma unroll
        for (int tn = 0; tn < 8; tn++)
#pragma unroll
            for (int j = 0; j < 4; j++) acc[tm][tn][j] = 0.f;

    const uint32_t aLaneOff =
        (uint32_t)((wm * 32 + (quad & 1) * 8 + qr) * KPAD + (quad >> 1) * 8) * 2;
    const uint32_t bLaneOff =
        (uint32_t)((wn * 64 + (quad >> 1) * 8 + qr) * KPAD + (quad & 1) * 8) * 2;

    auto mma_tile = [&](int buf) {
        const uint32_t sAh = smbase + buf * BUF_HALFS * 2;
        const uint32_t sAl = sAh + TILE_HALFS * 2;
        const uint32_t sBh = sAh + 2 * TILE_HALFS * 2;
        const uint32_t sBl = sAh + 3 * TILE_HALFS * 2;
#pragma unroll
        for (int ks = 0; ks < 32; ks += 16) {
            uint32_t ah[2][4], al[2][4];
#pragma unroll
            for (int tm = 0; tm < 2; tm++) {
                uint32_t off = aLaneOff + (uint32_t)(tm * 16 * KPAD + ks) * 2;
                ldsm_x4(ah[tm][0], ah[tm][1], ah[tm][2], ah[tm][3], sAh + off);
                ldsm_x4(al[tm][0], al[tm][1], al[tm][2], al[tm][3], sAl + off);
            }
#pragma unroll
            for (int tp = 0; tp < 4; tp++) {
                uint32_t off = bLaneOff + (uint32_t)(tp * 16 * KPAD + ks) * 2;
                uint32_t bh[4], bl[4];
                ldsm_x4(bh[0], bh[1], bh[2], bh[3], sBh + off);
                ldsm_x4(bl[0], bl[1], bl[2], bl[3], sBl + off);
#pragma unroll
                for (int half = 0; half < 2; half++) {
                    const int tn = tp * 2 + half;
#pragma unroll
                    for (int tm = 0; tm < 2; tm++) {
                        mma16816(acc[tm][tn], ah[tm], &bh[half * 2]);
                        mma16816(acc[tm][tn], ah[tm], &bl[half * 2]);
                        mma16816(acc[tm][tn], al[tm], &bh[half * 2]);
                    }
                }
            }
        }
    };

    const int ntiles = K / 32;

    load_gmem(0);
    store_smem(0);
    load_gmem(32);
    __syncthreads();

    for (int t = 0; t < ntiles; t++) {
        mma_tile(t & 1);
        if (t + 1 < ntiles) {
            store_smem((t + 1) & 1);
            if (t + 2 < ntiles) load_gmem((t + 2) * 32);
        }
        __syncthreads();
    }

#pragma unroll
    for (int tm = 0; tm < 2; tm++) {
        int row0 = blockIdx.y * 128 + wm * 32 + tm * 16 + g;
#pragma unroll
        for (int tn = 0; tn < 8; tn++) {
            int col = blockIdx.x * 128 + wn * 64 + tn * 8 + 2 * cc;
            *(float2*)(C + (size_t)row0 * N + col) =
                make_float2(acc[tm][tn][0], acc[tm][tn][1]);
            *(float2*)(C + (size_t)(row0 + 8) * N + col) =
                make_float2(acc[tm][tn][2], acc[tm][tn][3]);
        }
    }
}

// ---------------- RoPE cos/sin table (fp64 for phase accuracy) -------------
__global__ void rope_table(const int* __restrict__ positions) {
    int idx = blockIdx.x * blockDim.x + threadIdx.x;
    if (idx >= 2048 * 64) return;
    int t = idx >> 6;
    int j = idx & 63;
    double inv = exp(-(double)j * (log(1.0e6) / 64.0));
    double f = (double)positions[t] * inv;
    g_cos[idx] = (float)cos(f);
    g_sin[idx] = (float)sin(f);
}

// ---------------- fused RMSNorm + RoPE for Q and K in one launch -----------
__global__ void rmsrope_both(float* __restrict__ Q, float* __restrict__ K,
                             const float* __restrict__ qw,
                             const float* __restrict__ kw) {
    int wg = (blockIdx.x * blockDim.x + threadIdx.x) >> 5;
    int lane = threadIdx.x & 31;

    float* x;
    int t;
    const float* w;
    if (wg < 2048 * 32) {
        t = wg >> 5;
        int h = wg & 31;
        x = Q + (size_t)t * 4096 + h * 128;
        w = qw;
    } else {
        int wg2 = wg - 2048 * 32;
        if (wg2 >= 2048 * 8) return;
        t = wg2 >> 3;
        int h = wg2 & 7;
        x = K + (size_t)t * 1024 + h * 128;
        w = kw;
    }

    float v0 = x[lane], v1 = x[lane + 32], v2 = x[lane + 64], v3 = x[lane + 96];
    float ss = v0 * v0 + v1 * v1 + v2 * v2 + v3 * v3;
#pragma unroll
    for (int off = 16; off > 0; off >>= 1) ss += __shfl_xor_sync(0xffffffffu, ss, off);
    float rms = rsqrtf(ss * (1.f / 128.f) + 1e-6f);

    v0 *= rms * w[lane];
    v1 *= rms * w[lane + 32];
    v2 *= rms * w[lane + 64];
    v3 *= rms * w[lane + 96];

    float c0 = g_cos[t * 64 + lane],      s0 = g_sin[t * 64 + lane];
    float c1 = g_cos[t * 64 + lane + 32], s1 = g_sin[t * 64 + lane + 32];

    x[lane]      = v0 * c0 - v2 * s0;
    x[lane + 64] = v2 * c0 + v0 * s0;
    x[lane + 32] = v1 * c1 - v3 * s1;
    x[lane + 96] = v3 * c1 + v1 * s1;
}

// ==================== tensor-core causal flash attention ===================
// 1 CTA = 128 q rows x 1 head. 8 warps, 16 q rows each. KV tiles of 64.
// All mma split-bf16 3-pass. S frags re-used as PV A-operand (FA2 style).
// smem: Qh/Ql [128][136], Kh/Kl [64][136], Vth/Vtl [128][72] (V transposed)
#define DPAD 136
#define VPAD 72
#define AQ_HALFS (128 * DPAD)
#define AK_HALFS (64 * DPAD)
#define AV_HALFS (128 * VPAD)
#define ATTN_SMEM_BYTES ((2 * AQ_HALFS + 2 * AK_HALFS + 2 * AV_HALFS) * 2)

__global__ __launch_bounds__(256) void attn_mma(const float* __restrict__ Q,
                                                const float* __restrict__ K,
                                                const float* __restrict__ V,
                                                float* __restrict__ O) {
    extern __shared__ __nv_bfloat16 asm_buf[];
    __nv_bfloat16* Qh = asm_buf;
    __nv_bfloat16* Ql = Qh + AQ_HALFS;
    __nv_bfloat16* Kh = Ql + AQ_HALFS;
    __nv_bfloat16* Kl = Kh + AK_HALFS;
    __nv_bfloat16* Vth = Kl + AK_HALFS;
    __nv_bfloat16* Vtl = Vth + AV_HALFS;

    const uint32_t sQh = smem_u32(Qh);
    const uint32_t sQl = smem_u32(Ql);
    const uint32_t sKh = smem_u32(Kh);
    const uint32_t sKl = smem_u32(Kl);
    const uint32_t sVh = smem_u32(Vth);
    const uint32_t sVl = smem_u32(Vtl);

    const int qbi = 15 - blockIdx.x;          // big q blocks first
    const int h = blockIdx.y;
    const int kvh = h >> 2;
    const int tid = threadIdx.x;
    const int lane = tid & 31;
    const int w = tid >> 5;
    const int g = lane >> 2;
    const int cc = lane & 3;
    const int quad = lane >> 3;
    const int qr = lane & 7;

    const int ntiles = 2 * (qbi + 1);
    const float scale = 0.08838834764831845f;

    // ---- load Q block (128 x 128), split hi/lo ----
    {
        const int row = tid >> 1;
        const int half = tid & 1;
        const float* qp = Q + (size_t)(qbi * 128 + row) * 4096 + h * 128 + half * 64;
#pragma unroll
        for (int i = 0; i < 32; i++) {
            float2 v = *(const float2*)(qp + 2 * i);
            uint32_t hh, ll;
            split2pack(v.x, v.y, hh, ll);
            int off = row * DPAD + half * 64 + 2 * i;
            *(uint32_t*)&Qh[off] = hh;
            *(uint32_t*)&Ql[off] = ll;
        }
    }

    // frag lane offsets (bytes)
    const uint32_t aQOff =
        (uint32_t)((w * 16 + (quad & 1) * 8 + qr) * DPAD + (quad >> 1) * 8) * 2;
    const uint32_t bKOff =
        (uint32_t)(((quad >> 1) * 8 + qr) * DPAD + (quad & 1) * 8) * 2;
    const uint32_t bVOff =
        (uint32_t)(((quad >> 1) * 8 + qr) * VPAD + (quad & 1) * 8) * 2;

    float oacc[16][4];
#pragma unroll
    for (int tn = 0; tn < 16; tn++)
#pragma unroll
        for (int j = 0; j < 4; j++) oacc[tn][j] = 0.f;

    float mA = -1e30f, mB = -1e30f, lA = 0.f, lB = 0.f;
    const int rowA = qbi * 128 + w * 16 + g;
    const int rowB = rowA + 8;

    __syncthreads();

    for (int kb = 0; kb < ntiles; kb++) {
        // ---- load K tile [64][128] -> Kh/Kl [kv][DPAD] ----
        {
            const int kv = tid >> 2;
            const int j = tid & 3;
            const float* kp = K + (size_t)(kb * 64 + kv) * 1024 + kvh * 128;
#pragma unroll
            for (int i = 0; i < 16; i++) {
                int d0 = 2 * (j + 4 * i);
                float2 v = *(const float2*)(kp + d0);
                uint32_t hh, ll;
                split2pack(v.x, v.y, hh, ll);
                int off = kv * DPAD + d0;
                *(uint32_t*)&Kh[off] = hh;
                *(uint32_t*)&Kl[off] = ll;
            }
        }
        // ---- load V tile transposed -> Vth/Vtl [d][VPAD] ----
        {
            const int d = tid & 127;
            const int half = tid >> 7;
            const float* vp = V + (size_t)(kb * 64) * 1024 + kvh * 128 + d;
#pragma unroll
            for (int i = 0; i < 16; i++) {
                int kp2 = half * 16 + i;
                float v0 = vp[(size_t)(2 * kp2) * 1024];
                float v1 = vp[(size_t)(2 * kp2 + 1) * 1024];
                uint32_t hh, ll;
                split2pack(v0, v1, hh, ll);
                int off = d * VPAD + 2 * kp2;
                *(uint32_t*)&Vth[off] = hh;
                *(uint32_t*)&Vtl[off] = ll;
            }
        }
        __syncthreads();

        // ---- S = Q K^T (3-pass split), S warp tile 16 x 64 ----
        float sacc[8][4];
#pragma unroll
        for (int tn = 0; tn < 8; tn++)
#pragma unroll
            for (int j = 0; j < 4; j++) sacc[tn][j] = 0.f;

#pragma unroll
        for (int ks = 0; ks < 128; ks += 16) {
            uint32_t ah[4], al[4];
            uint32_t aoff = aQOff + (uint32_t)ks * 2;
            ldsm_x4(ah[0], ah[1], ah[2], ah[3], sQh + aoff);
            ldsm_x4(al[0], al[1], al[2], al[3], sQl + aoff);
#pragma unroll
            for (int p = 0; p < 4; p++) {
                uint32_t boff = bKOff + (uint32_t)(p * 16 * DPAD + ks) * 2;
                uint32_t bh[4], bl[4];
                ldsm_x4(bh[0], bh[1], bh[2], bh[3], sKh + boff);
                ldsm_x4(bl[0], bl[1], bl[2], bl[3], sKl + boff);
#pragma unroll
                for (int half = 0; half < 2; half++) {
                    const int tn = 2 * p + half;
                    mma16816(sacc[tn], ah, &bh[half * 2]);
                    mma16816(sacc[tn], ah, &bl[half * 2]);
                    mma16816(sacc[tn], al, &bh[half * 2]);
                }
            }
        }

        // ---- softmax on fragments ----
        float mxA = -1e30f, mxB = -1e30f;
#pragma unroll
        for (int tn = 0; tn < 8; tn++) {
            int colbase = kb * 64 + tn * 8 + 2 * cc;
            float s0 = sacc[tn][0] * scale;
            float s1 = sacc[tn][1] * scale;
            float s2 = sacc[tn][2] * scale;
            float s3 = sacc[tn][3] * scale;
            if (colbase > rowA) s0 = -1e30f;
            if (colbase + 1 > rowA) s1 = -1e30f;
            if (colbase > rowB) s2 = -1e30f;
            if (colbase + 1 > rowB) s3 = -1e30f;
            sacc[tn][0] = s0; sacc[tn][1] = s1;
            sacc[tn][2] = s2; sacc[tn][3] = s3;
            mxA = fmaxf(mxA, fmaxf(s0, s1));
            mxB = fmaxf(mxB, fmaxf(s2, s3));
        }
        mxA = fmaxf(mxA, __shfl_xor_sync(0xffffffffu, mxA, 1));
        mxA = fmaxf(mxA, __shfl_xor_sync(0xffffffffu, mxA, 2));
        mxB = fmaxf(mxB, __shfl_xor_sync(0xffffffffu, mxB, 1));
        mxB = fmaxf(mxB, __shfl_xor_sync(0xffffffffu, mxB, 2));

        float mnA = fmaxf(mA, mxA);
        float mnB = fmaxf(mB, mxB);
        float corrA = __expf(mA - mnA);
        float corrB = __expf(mB - mnB);
        mA = mnA;
        mB = mnB;

        float sumA = 0.f, sumB = 0.f;
#pragma unroll
        for (int tn = 0; tn < 8; tn++) {
            float p0 = __expf(sacc[tn][0] - mnA);
            float p1 = __expf(sacc[tn][1] - mnA);
            float p2 = __expf(sacc[tn][2] - mnB);
            float p3 = __expf(sacc[tn][3] - mnB);
            sacc[tn][0] = p0; sacc[tn][1] = p1;
            sacc[tn][2] = p2; sacc[tn][3] = p3;
            sumA += p0 + p1;
            sumB += p2 + p3;
        }
        sumA += __shfl_xor_sync(0xffffffffu, sumA, 1);
        sumA += __shfl_xor_sync(0xffffffffu, sumA, 2);
        sumB += __shfl_xor_sync(0xffffffffu, sumB, 1);
        sumB += __shfl_xor_sync(0xffffffffu, sumB, 2);
        lA = lA * corrA + sumA;
        lB = lB * corrB + sumB;

#pragma unroll
        for (int tn = 0; tn < 16; tn++) {
            oacc[tn][0] *= corrA;
            oacc[tn][1] *= corrA;
            oacc[tn][2] *= corrB;
            oacc[tn][3] *= corrB;
        }

        // ---- O += P V (3-pass split); P frags built from sacc in regs ----
#pragma unroll
        for (int j = 0; j < 4; j++) {
            uint32_t pah[4], pal[4];
            split2pack(sacc[2 * j][0], sacc[2 * j][1], pah[0], pal[0]);
            split2pack(sacc[2 * j][2], sacc[2 * j][3], pah[1], pal[1]);
            split2pack(sacc[2 * j + 1][0], sacc[2 * j + 1][1], pah[2], pal[2]);
            split2pack(sacc[2 * j + 1][2], sacc[2 * j + 1][3], pah[3], pal[3]);
#pragma unroll
            for (int p = 0; p < 8; p++) {
                uint32_t voff = bVOff + (uint32_t)(p * 16 * VPAD + j * 16) * 2;
                uint32_t bh[4], bl[4];
                ldsm_x4(bh[0], bh[1], bh[2], bh[3], sVh + voff);
                ldsm_x4(bl[0], bl[1], bl[2], bl[3], sVl + voff);
#pragma unroll
                for (int half = 0; half < 2; half++) {
                    const int tn = 2 * p + half;
                    mma16816(oacc[tn], pah, &bh[half * 2]);
                    mma16816(oacc[tn], pah, &bl[half * 2]);
                    mma16816(oacc[tn], pal, &bh[half * 2]);
                }
            }
        }
        __syncthreads();
    }

    // ---- epilogue ----
    const float invA = 1.f / lA;
    const float invB = 1.f / lB;
#pragma unroll
    for (int tn = 0; tn < 16; tn++) {
        int d = tn * 8 + 2 * cc;
        *(float2*)(O + (size_t)rowA * 4096 + h * 128 + d) =
            make_float2(oacc[tn][0] * invA, oacc[tn][1] * invA);
        *(float2*)(O + (size_t)rowB * 4096 + h * 128 + d) =
            make_float2(oacc[tn][2] * invB, oacc[tn][3] * invB);
    }
}

// ---------------- launch ----------------------------------------------------
extern "C" void kernel_launch(void* const* d_in, const int* in_sizes, int n_in,
                              void* d_out, int out_size) {
    const float* hidden    = (const float*)d_in[0];
    const int*   positions = (const int*)d_in[1];
    const float* Wq        = (const float*)d_in[2];
    const float* Wk        = (const float*)d_in[3];
    const float* Wv        = (const float*)d_in[4];
    const float* Wo        = (const float*)d_in[5];
    const float* q_norm_w  = (const float*)d_in[6];
    const float* k_norm_w  = (const float*)d_in[7];
    float* out = (float*)d_out;

    float* q;    cudaGetSymbolAddress((void**)&q, g_q);
    float* k;    cudaGetSymbolAddress((void**)&k, g_k);
    float* v;    cudaGetSymbolAddress((void**)&v, g_v);
    float* attn; cudaGetSymbolAddress((void**)&attn, g_attn);

    cudaFuncSetAttribute(hgemm2, cudaFuncAttributeMaxDynamicSharedMemorySize,
                         GEMM_SMEM_BYTES);
    cudaFuncSetAttribute(attn_mma, cudaFuncAttributeMaxDynamicSharedMemorySize,
                         ATTN_SMEM_BYTES);

    // 1: rope table
    rope_table<<<(2048 * 64 + 255) / 256, 256>>>(positions);

    // 2-4: QKV projections
    hgemm2<<<dim3(32, 16), 256, GEMM_SMEM_BYTES>>>(hidden, Wq, q, 2048, 4096, 4096);
    hgemm2<<<dim3(8, 16), 256, GEMM_SMEM_BYTES>>>(hidden, Wk, k, 2048, 1024, 4096);
    hgemm2<<<dim3(8, 16), 256, GEMM_SMEM_BYTES>>>(hidden, Wv, v, 2048, 1024, 4096);

    // 5: fused rmsnorm+rope
    rmsrope_both<<<(2048 * 40) / 8, 256>>>(q, k, q_norm_w, k_norm_w);

    // 6: attention (tensor cores)
    attn_mma<<<dim3(16, 32), 256, ATTN_SMEM_BYTES>>>(q, k, v, attn);

    // 7: output projection
    hgemm2<<<dim3(32, 16), 256, GEMM_SMEM_BYTES>>>(attn, Wo, out, 2048, 4096, 4096);
}